// round 15
// baseline (speedup 1.0000x reference)
#include <cuda_runtime.h>
#include <cuda_bf16.h>
#include <cstdint>

// ============================================================================
// S = 256 states/vocab, B = 16 sequences, L = 512 tokens.
// sparsemax_loss_vec(z)[y] = C(z) - z[y], C(z) = tau + 0.5*sum(p^2) + 0.5
// Backward recurrence (log semiring):
//   c_t[q] = G[x][q] + log( sum_n exp(-T[q,x,n]) * exp(c_{t+1}[n] - cmax) ) + cmax
//   G[x][q] = cE[q] - E[q,x] + cT[q,x]
// out = sum_b LSE_q( (cA - alpha[q]) + c_0[b,q] ),  c_L[q] = cOmega - omega[q]
//
// R13 (= R11 resubmitted; R12 was an infra flake, cf. R3 with the empty stub):
//  - M table f32 (67MB, L2-resident): kills the 64 bf16-unpack ALU ops per
//    thread per step (MAC issue floor 544 -> ~380 cyc).
//  - Chart exchange: reducers write locally, then ONE cp.async.bulk (512B)
//    to the peer with a single complete_tx -- replaces 128 scalar st.async
//    (one tx-update instead of 128 on the receiving mbarrier).
//  - cmax CTA-local (own chart value: exact math, no peer dependency);
//    own-n-half warps never wait, peer-half warps wait on the mbarrier.
// ============================================================================

#define SS 256
#define BB 16
#define LL 512
#define NT 512

// -------- device scratch --------
__device__ float g_cT[SS * SS];
__device__ float g_cE[SS];
__device__ float g_Gtab[SS * SS];            // [x][q]
__device__ float g_c0[SS];
__device__ float g_LAl[SS];
__device__ float g_Mf[(size_t)SS * SS * SS]; // [x][n][q] = exp(-T[q,x,n]), f32
__device__ float g_perseq[BB];

// -------- helpers --------
__device__ __forceinline__ float wredMax(float v) {
#pragma unroll
    for (int o = 16; o; o >>= 1) v = fmaxf(v, __shfl_xor_sync(0xffffffffu, v, o));
    return v;
}
__device__ __forceinline__ float wredSum(float v) {
#pragma unroll
    for (int o = 16; o; o >>= 1) v += __shfl_xor_sync(0xffffffffu, v, o);
    return v;
}

// MUFU-free exp (|x| <= ~0.8 here)
__device__ __forceinline__ float exp_poly(float x) {
    float y = x * 1.44269504088896341f;
    float n = rintf(y);
    float t = (y - n) * 0.6931471805599453f;
    float p = 1.98412698412698413e-4f;
    p = fmaf(p, t, 1.38888888888888889e-3f);
    p = fmaf(p, t, 8.33333333333333333e-3f);
    p = fmaf(p, t, 4.16666666666666667e-2f);
    p = fmaf(p, t, 1.66666666666666667e-1f);
    p = fmaf(p, t, 0.5f);
    p = fmaf(p, t, 1.0f);
    p = fmaf(p, t, 1.0f);
    return p * __int_as_float(((int)n + 127) << 23);
}

// C(z) via Newton on f(tau) = sum relu(z - tau) - 1 (bit-identical output vs
// bisection across R6-R10; C stationary in tau at the optimum).
__device__ __forceinline__ float sparse_c8(const float v[8]) {
    float zmax = v[0];
#pragma unroll
    for (int i = 1; i < 8; i++) zmax = fmaxf(zmax, v[i]);
    zmax = wredMax(zmax);
    float tau = zmax - 1.0f;
#pragma unroll 1
    for (int it = 0; it < 24; ++it) {
        float sl = 0.0f, kl = 0.0f;
#pragma unroll
        for (int i = 0; i < 8; i++) {
            float d = v[i] - tau;
            if (d > 0.0f) { sl += d; kl += 1.0f; }
        }
#pragma unroll
        for (int o = 16; o; o >>= 1) {
            sl += __shfl_xor_sync(0xffffffffu, sl, o);
            kl += __shfl_xor_sync(0xffffffffu, kl, o);
        }
        float f = sl - 1.0f;
        if (f <= 1e-6f) break;            // warp-uniform
        tau += __fdividef(f, kl);
    }
    float s2 = 0.0f;
#pragma unroll
    for (int i = 0; i < 8; i++) {
        float p = fmaxf(v[i] - tau, 0.0f);
        s2 = fmaf(p, p, s2);
    }
    s2 = wredSum(s2);
    return tau + 0.5f * s2 + 0.5f;
}

__device__ __forceinline__ void load_row8(const float* __restrict__ z, int lane, float v[8]) {
    const float4* z4 = reinterpret_cast<const float4*>(z);
    float4 a = z4[lane];
    float4 b = z4[lane + 32];
    v[0] = a.x; v[1] = a.y; v[2] = a.z; v[3] = a.w;
    v[4] = b.x; v[5] = b.y; v[6] = b.z; v[7] = b.w;
}

// -------- K1: per-row C for all 65536 rows of T --------
__global__ void __launch_bounds__(256) k_rowconst_T(const float* __restrict__ T) {
    int warp = (blockIdx.x * blockDim.x + threadIdx.x) >> 5;
    int lane = threadIdx.x & 31;
    float v[8];
    load_row8(T + (size_t)warp * SS, lane, v);
    float c = sparse_c8(v);
    if (lane == 0) g_cT[warp] = c;
}

// -------- K2: C for E rows, alpha, omega --------
__global__ void __launch_bounds__(256) k_small(const float* __restrict__ E,
                                               const float* __restrict__ al,
                                               const float* __restrict__ om) {
    int warp = (blockIdx.x * blockDim.x + threadIdx.x) >> 5;
    int lane = threadIdx.x & 31;
    float v[8];
    if (warp < SS) {
        load_row8(E + (size_t)warp * SS, lane, v);
        float c = sparse_c8(v);
        if (lane == 0) g_cE[warp] = c;
    } else if (warp == SS) {
        load_row8(al, lane, v);
        float c = sparse_c8(v);
#pragma unroll
        for (int i = 0; i < 8; i++) g_LAl[lane + 32 * i] = c - al[lane + 32 * i];
    } else if (warp == SS + 1) {
        load_row8(om, lane, v);
        float c = sparse_c8(v);
#pragma unroll
        for (int i = 0; i < 8; i++) g_c0[lane + 32 * i] = c - om[lane + 32 * i];
    }
}

// -------- K3: G[x][q] --------
__global__ void __launch_bounds__(256) k_gtab(const float* __restrict__ E) {
    int x = blockIdx.x, q = threadIdx.x;
    g_Gtab[x * SS + q] = g_cE[q] - E[q * SS + x] + g_cT[q * SS + x];
}

// -------- K4: Mf[x][n][q] = exp(-T[q][x][n]) via tiled smem transpose --------
__global__ void __launch_bounds__(256) k_buildM(const float* __restrict__ T) {
    __shared__ float tile[32][33];
    int x  = blockIdx.z;
    int q0 = blockIdx.x << 5, n0 = blockIdx.y << 5;
    int tx = threadIdx.x, ty = threadIdx.y;
#pragma unroll
    for (int i = 0; i < 32; i += 8) {
        int q = q0 + ty + i;
        tile[ty + i][tx] = T[(unsigned)q * 65536u + (unsigned)x * 256u + n0 + tx];
    }
    __syncthreads();
#pragma unroll
    for (int i = 0; i < 32; i += 8) {
        int n = n0 + ty + i;
        g_Mf[((size_t)x << 16) + (size_t)(n << 8) + (q0 + tx)]
            = exp_poly(-tile[tx][ty + i]);
    }
}

// -------- cluster primitives --------
__device__ __forceinline__ unsigned smem_u32(const void* p) {
    return (unsigned)__cvta_generic_to_shared(p);
}
__device__ __forceinline__ unsigned mapa_u32(unsigned local_smem, unsigned target_rank) {
    unsigned remote;
    asm volatile("mapa.shared::cluster.u32 %0, %1, %2;"
                 : "=r"(remote) : "r"(local_smem), "r"(target_rank));
    return remote;
}
__device__ __forceinline__ void cluster_sync_() {
    asm volatile("barrier.cluster.arrive.aligned;" ::: "memory");
    asm volatile("barrier.cluster.wait.aligned;"   ::: "memory");
}
__device__ __forceinline__ void mbar_wait_cta(unsigned addr, unsigned parity) {
    asm volatile(
        "{\n\t.reg .pred P;\n\t"
        "WAITLOOP_%=:\n\t"
        "mbarrier.try_wait.parity.acquire.cta.shared::cta.b64 P, [%0], %1, 0x989680;\n\t"
        "@P bra.uni WAITDONE_%=;\n\t"
        "bra.uni WAITLOOP_%=;\n\t"
        "WAITDONE_%=:\n\t}"
        :: "r"(addr), "r"(parity) : "memory");
}

// -------- K5: backward recursion, one batch per 2-CTA cluster --------------
// CTA rank r owns q,n in [128r, 128r+128). Warp w covers n in [16w, 16w+16);
// lane covers 4 consecutive q. Own-half warps never wait; peer-half warps
// wait on the pairwise mbarrier fed by one bulk 512B copy per step.
__global__ void __cluster_dims__(2, 1, 1) __launch_bounds__(NT, 1)
k_forward(const int* __restrict__ xs) {
    __shared__ __align__(16) float cbuf[2][SS];         // full chart, dbl buffered
    __shared__ __align__(16) float sew[16][16];         // per-warp se slice
    __shared__ __align__(16) float spart[16 * 128];     // 16 n-groups x 128 q
    __shared__ int   sx[LL];
    __shared__ __align__(8) unsigned long long bars[2];

    const int tid  = threadIdx.x;
    const int lane = tid & 31, wid = tid >> 5;
    const unsigned rank = (unsigned)(blockIdx.x & 1);
    const unsigned peer = rank ^ 1u;
    const int b  = blockIdx.x >> 1;
    const int qbase = (int)rank * 128;
    const bool ownw = ((wid < 8) == (rank == 0));       // warp's n-half is local

    if (tid < LL) sx[tid] = xs[b * LL + tid];
    if (tid < SS) cbuf[0][tid] = g_c0[tid];
    if (tid == 0) {
        asm volatile("mbarrier.init.shared.b64 [%0], %1;"
                     :: "r"(smem_u32(&bars[0])), "r"(1) : "memory");
        asm volatile("mbarrier.init.shared.b64 [%0], %1;"
                     :: "r"(smem_u32(&bars[1])), "r"(1) : "memory");
    }
    __syncthreads();
    cluster_sync_();   // inits visible before any bulk copy

    const unsigned bar0_loc = smem_u32(&bars[0]);
    const unsigned bar1_loc = smem_u32(&bars[1]);
    const unsigned bar_rem0 = mapa_u32(bar0_loc, peer);
    const unsigned bar_rem1 = mapa_u32(bar1_loc, peer);
    // bulk-copy src (local own half) and dst (same slot in peer's buffers)
    const unsigned src_loc0 = smem_u32(&cbuf[0][qbase]);
    const unsigned src_loc1 = smem_u32(&cbuf[1][qbase]);
    const unsigned dst_rem0 = mapa_u32(src_loc0, peer);
    const unsigned dst_rem1 = mapa_u32(src_loc1, peer);

    float4 PF[16];                        // 16 n x 4 q of f32 M (64 regs)

#define PFETCH(xv) do {                                                           \
    const float4* _mp = (const float4*)g_Mf + (((size_t)(unsigned)(xv)) << 14)    \
                        + (unsigned)(wid << 10) + (unsigned)((qbase >> 2) + lane);\
    _Pragma("unroll")                                                             \
    for (int _j = 0; _j < 16; _j++) PF[_j] = __ldg(_mp + (_j << 6));              \
} while (0)

    float gcur = (tid < 128) ? g_Gtab[sx[LL - 1] * SS + qbase + tid] : 0.0f;
    PFETCH(sx[LL - 1]);

    unsigned ph0 = 0, ph1 = 0;
#pragma unroll 1
    for (int s = 0; s < LL; ++s) {
        const int p = s & 1, np = p ^ 1;
        const int x = sx[LL - 1 - s];

        // arm receive barrier for NEXT incoming peer half (one 512B bulk copy)
        if (tid == 0)
            asm volatile("mbarrier.arrive.expect_tx.shared.b64 _, [%0], %1;"
                         :: "r"(np ? bar1_loc : bar0_loc), "r"(512) : "memory");
        __syncthreads();                       // S1: local chart writes visible

        if (s) {
            unsigned& ph = p ? ph1 : ph0;
            if (!ownw) mbar_wait_cta(p ? bar1_loc : bar0_loc, ph);
            ph ^= 1;                           // all threads track parity
        }

        // CTA-local shift (own-half value: exact math, any uniform shift ok)
        float cmaxl = cbuf[p][qbase];
        if (lane < 16)
            sew[wid][lane] = __expf(cbuf[p][(wid << 4) + lane] - cmaxl);
        __syncwarp();

        float a0 = 0.f, a1 = 0.f, a2 = 0.f, a3 = 0.f;
        const float4* sv4 = (const float4*)sew[wid];
#pragma unroll
        for (int g = 0; g < 4; ++g) {
            float4 sv = sv4[g];
            float4 m0 = PF[4 * g + 0];
            float4 m1 = PF[4 * g + 1];
            float4 m2 = PF[4 * g + 2];
            float4 m3 = PF[4 * g + 3];
            a0 = fmaf(m0.x, sv.x, a0); a1 = fmaf(m0.y, sv.x, a1);
            a2 = fmaf(m0.z, sv.x, a2); a3 = fmaf(m0.w, sv.x, a3);
            a0 = fmaf(m1.x, sv.y, a0); a1 = fmaf(m1.y, sv.y, a1);
            a2 = fmaf(m1.z, sv.y, a2); a3 = fmaf(m1.w, sv.y, a3);
            a0 = fmaf(m2.x, sv.z, a0); a1 = fmaf(m2.y, sv.z, a1);
            a2 = fmaf(m2.z, sv.z, a2); a3 = fmaf(m2.w, sv.z, a3);
            a0 = fmaf(m3.x, sv.w, a0); a1 = fmaf(m3.y, sv.w, a1);
            a2 = fmaf(m3.z, sv.w, a2); a3 = fmaf(m3.w, sv.w, a3);
        }
        *(float4*)&spart[(wid << 7) + (lane << 2)] = make_float4(a0, a1, a2, a3);

        // prefetch next step's M and G while partials settle / peer lags
        int xn = (s + 1 < LL) ? sx[LL - 2 - s] : 0;
        PFETCH(xn);
        float gnext = (tid < 128) ? g_Gtab[xn * SS + qbase + tid] : 0.0f;

        __syncthreads();                       // S3: partials visible

        if (tid < 128) {
            float ssum = 0.f;
#pragma unroll
            for (int g = 0; g < 16; ++g) ssum += spart[(g << 7) + tid];
            float nc = (x != 0) ? (gcur + __logf(ssum) + cmaxl)
                                : cbuf[p][qbase + tid];       // padding passthrough
            cbuf[np][qbase + tid] = nc;                       // own half, local STS
            asm volatile("bar.sync 1, 128;" ::: "memory");    // reducer warps only
            if (tid == 0) {
                asm volatile("fence.proxy.async.shared::cta;" ::: "memory");
                asm volatile(
                    "cp.async.bulk.shared::cluster.shared::cta.mbarrier::complete_tx::bytes "
                    "[%0], [%1], %2, [%3];"
                    :: "r"(np ? dst_rem1 : dst_rem0),
                       "r"(np ? src_loc1 : src_loc0),
                       "r"(512),
                       "r"(np ? bar_rem1 : bar_rem0) : "memory");
            }
        }
        gcur = gnext;
    }

    // step 511 wrote into cbuf[0] / bars[0] (phase parity = ph0)
    mbar_wait_cta(bar0_loc, ph0);
    __syncthreads();

    if (rank == 0 && wid == 0) {
        float vv[8];
        float m = -3.0e38f;
#pragma unroll
        for (int i = 0; i < 8; i++) {
            vv[i] = g_LAl[lane + 32 * i] + cbuf[0][lane + 32 * i];
            m = fmaxf(m, vv[i]);
        }
        m = wredMax(m);
        float sacc = 0.0f;
#pragma unroll
        for (int i = 0; i < 8; i++) sacc += __expf(vv[i] - m);
        sacc = wredSum(sacc);
        if (lane == 0) g_perseq[b] = __logf(sacc) + m;
    }
    cluster_sync_();   // no CTA exits while peer bulk copies may target it
#undef PFETCH
}

// -------- K6: out = sum_b per_seq[b] --------
__global__ void k_final(float* __restrict__ out) {
    float v = (threadIdx.x < BB) ? g_perseq[threadIdx.x] : 0.0f;
    v = wredSum(v);
    if (threadIdx.x == 0) out[0] = v;
}

// ============================================================================
extern "C" void kernel_launch(void* const* d_in, const int* in_sizes, int n_in,
                              void* d_out, int out_size) {
    const int*   xs    = (const int*)d_in[0];
    const float* alpha = (const float*)d_in[1];
    const float* omega = (const float*)d_in[2];
    const float* E     = (const float*)d_in[3];
    const float* T     = (const float*)d_in[4];
    float* out = (float*)d_out;

    k_rowconst_T<<<(SS * SS) / 8, 256>>>(T);
    k_small<<<33, 256>>>(E, alpha, omega);
    k_gtab<<<SS, 256>>>(E);
    k_buildM<<<dim3(8, 8, SS), dim3(32, 8)>>>(T);
    k_forward<<<BB * 2, NT>>>(xs);        // 16 clusters x 2 CTAs x 512 threads
    k_final<<<1, 32>>>(out);
}

// round 17
// speedup vs baseline: 1.4694x; 1.4694x over previous
#include <cuda_runtime.h>
#include <cuda_bf16.h>
#include <cstdint>

// ============================================================================
// S = 256 states/vocab, B = 16 sequences, L = 512 tokens.
// sparsemax_loss_vec(z)[y] = C(z) - z[y], C(z) = tau + 0.5*sum(p^2) + 0.5
// Backward recurrence (log semiring):
//   c_t[q] = G[x][q] + log( sum_n exp(-T[q,x,n]) * exp(c_{t+1}[n] - cmax) ) + cmax
//   G[x][q] = cE[q] - E[q,x] + cT[q,x]
// out = sum_b LSE_q( (cA - alpha[q]) + c_0[b,q] ),  c_L[q] = cOmega - omega[q]
//
// R16: R15 showed the binding constraint is the per-SM L1 byte wall of the M
// stream (f32 table = +512 wavefront-cyc/step = exactly the regression).
//  -> bf16 paired-n table again (R10), AND 4-CTA clusters per batch: each CTA
//     owns 64 q -> 32KB/step/SM (256 wavefront-cyc wall, half of R10).
//  -> exchange: 64-float own chunk, 3 bulk 256B copies to peers, receiver
//     expects 768B on one mbarrier (3 tx-updates/step; R6's failure was 256).
//  -> cmax CTA-local; own-n warps ((wid>>2)==rank) never wait.
// ============================================================================

#define SS 256
#define BB 16
#define LL 512
#define NT 512
#define CL 4

// -------- device scratch --------
__device__ float    g_cT[SS * SS];
__device__ float    g_cE[SS];
__device__ float    g_Gtab[SS * SS];                 // [x][q]
__device__ float    g_c0[SS];
__device__ float    g_LAl[SS];
__device__ unsigned g_M2[(size_t)SS * SS * SS / 2];  // [x][n/2][q]: bf16(n)|bf16(n+1)<<16
__device__ float    g_perseq[BB];

// -------- helpers --------
__device__ __forceinline__ float wredMax(float v) {
#pragma unroll
    for (int o = 16; o; o >>= 1) v = fmaxf(v, __shfl_xor_sync(0xffffffffu, v, o));
    return v;
}
__device__ __forceinline__ float wredSum(float v) {
#pragma unroll
    for (int o = 16; o; o >>= 1) v += __shfl_xor_sync(0xffffffffu, v, o);
    return v;
}

// MUFU-free exp (|x| <= ~0.8 here)
__device__ __forceinline__ float exp_poly(float x) {
    float y = x * 1.44269504088896341f;
    float n = rintf(y);
    float t = (y - n) * 0.6931471805599453f;
    float p = 1.98412698412698413e-4f;
    p = fmaf(p, t, 1.38888888888888889e-3f);
    p = fmaf(p, t, 8.33333333333333333e-3f);
    p = fmaf(p, t, 4.16666666666666667e-2f);
    p = fmaf(p, t, 1.66666666666666667e-1f);
    p = fmaf(p, t, 0.5f);
    p = fmaf(p, t, 1.0f);
    p = fmaf(p, t, 1.0f);
    return p * __int_as_float(((int)n + 127) << 23);
}

// C(z) via Newton on f(tau) = sum relu(z - tau) - 1.
__device__ __forceinline__ float sparse_c8(const float v[8]) {
    float zmax = v[0];
#pragma unroll
    for (int i = 1; i < 8; i++) zmax = fmaxf(zmax, v[i]);
    zmax = wredMax(zmax);
    float tau = zmax - 1.0f;
#pragma unroll 1
    for (int it = 0; it < 24; ++it) {
        float sl = 0.0f, kl = 0.0f;
#pragma unroll
        for (int i = 0; i < 8; i++) {
            float d = v[i] - tau;
            if (d > 0.0f) { sl += d; kl += 1.0f; }
        }
#pragma unroll
        for (int o = 16; o; o >>= 1) {
            sl += __shfl_xor_sync(0xffffffffu, sl, o);
            kl += __shfl_xor_sync(0xffffffffu, kl, o);
        }
        float f = sl - 1.0f;
        if (f <= 1e-6f) break;            // warp-uniform
        tau += __fdividef(f, kl);
    }
    float s2 = 0.0f;
#pragma unroll
    for (int i = 0; i < 8; i++) {
        float p = fmaxf(v[i] - tau, 0.0f);
        s2 = fmaf(p, p, s2);
    }
    s2 = wredSum(s2);
    return tau + 0.5f * s2 + 0.5f;
}

__device__ __forceinline__ void load_row8(const float* __restrict__ z, int lane, float v[8]) {
    const float4* z4 = reinterpret_cast<const float4*>(z);
    float4 a = z4[lane];
    float4 b = z4[lane + 32];
    v[0] = a.x; v[1] = a.y; v[2] = a.z; v[3] = a.w;
    v[4] = b.x; v[5] = b.y; v[6] = b.z; v[7] = b.w;
}

// -------- K1: per-row C for all 65536 rows of T --------
__global__ void __launch_bounds__(256) k_rowconst_T(const float* __restrict__ T) {
    int warp = (blockIdx.x * blockDim.x + threadIdx.x) >> 5;
    int lane = threadIdx.x & 31;
    float v[8];
    load_row8(T + (size_t)warp * SS, lane, v);
    float c = sparse_c8(v);
    if (lane == 0) g_cT[warp] = c;
}

// -------- K2: C for E rows, alpha, omega --------
__global__ void __launch_bounds__(256) k_small(const float* __restrict__ E,
                                               const float* __restrict__ al,
                                               const float* __restrict__ om) {
    int warp = (blockIdx.x * blockDim.x + threadIdx.x) >> 5;
    int lane = threadIdx.x & 31;
    float v[8];
    if (warp < SS) {
        load_row8(E + (size_t)warp * SS, lane, v);
        float c = sparse_c8(v);
        if (lane == 0) g_cE[warp] = c;
    } else if (warp == SS) {
        load_row8(al, lane, v);
        float c = sparse_c8(v);
#pragma unroll
        for (int i = 0; i < 8; i++) g_LAl[lane + 32 * i] = c - al[lane + 32 * i];
    } else if (warp == SS + 1) {
        load_row8(om, lane, v);
        float c = sparse_c8(v);
#pragma unroll
        for (int i = 0; i < 8; i++) g_c0[lane + 32 * i] = c - om[lane + 32 * i];
    }
}

// -------- K3: G[x][q] --------
__global__ void __launch_bounds__(256) k_gtab(const float* __restrict__ E) {
    int x = blockIdx.x, q = threadIdx.x;
    g_Gtab[x * SS + q] = g_cE[q] - E[q * SS + x] + g_cT[q * SS + x];
}

// -------- K4: M2[x][n/2][q] = pack(bf16(exp(-T[q,x,n])), bf16(exp(-T[q,x,n+1]))) --------
__global__ void __launch_bounds__(256) k_buildM(const float* __restrict__ T) {
    __shared__ float tile[32][33];
    int x  = blockIdx.z;
    int q0 = blockIdx.x << 5, n0 = blockIdx.y << 5;
    int tx = threadIdx.x, ty = threadIdx.y;
#pragma unroll
    for (int i = 0; i < 32; i += 8) {
        int q = q0 + ty + i;
        tile[ty + i][tx] = T[(unsigned)q * 65536u + (unsigned)x * 256u + n0 + tx];
    }
    __syncthreads();
#pragma unroll
    for (int i = 0; i < 16; i += 8) {
        int npl = ty + i;                      // 0..15 local npair
        float v0 = exp_poly(-tile[tx][2 * npl]);
        float v1 = exp_poly(-tile[tx][2 * npl + 1]);
        __nv_bfloat162 h2 = __floats2bfloat162_rn(v0, v1);   // low = n even
        g_M2[((size_t)x << 15) + (size_t)(((n0 >> 1) + npl) << 8) + (q0 + tx)]
            = *reinterpret_cast<unsigned*>(&h2);
    }
}

// -------- cluster primitives --------
__device__ __forceinline__ unsigned smem_u32(const void* p) {
    return (unsigned)__cvta_generic_to_shared(p);
}
__device__ __forceinline__ unsigned mapa_u32(unsigned local_smem, unsigned target_rank) {
    unsigned remote;
    asm volatile("mapa.shared::cluster.u32 %0, %1, %2;"
                 : "=r"(remote) : "r"(local_smem), "r"(target_rank));
    return remote;
}
__device__ __forceinline__ void cluster_sync_() {
    asm volatile("barrier.cluster.arrive.aligned;" ::: "memory");
    asm volatile("barrier.cluster.wait.aligned;"   ::: "memory");
}
__device__ __forceinline__ void mbar_wait_cta(unsigned addr, unsigned parity) {
    asm volatile(
        "{\n\t.reg .pred P;\n\t"
        "WAITLOOP_%=:\n\t"
        "mbarrier.try_wait.parity.acquire.cta.shared::cta.b64 P, [%0], %1, 0x989680;\n\t"
        "@P bra.uni WAITDONE_%=;\n\t"
        "bra.uni WAITLOOP_%=;\n\t"
        "WAITDONE_%=:\n\t}"
        :: "r"(addr), "r"(parity) : "memory");
}

// -------- K5: backward recursion, one batch per 4-CTA cluster --------------
// CTA rank r owns q in [64r, 64r+64) and n-chunk [64r, 64r+64). Warp w covers
// n in [16w, 16w+16); within a warp, lane half lh = lane>>4 covers 8 of those
// 16 n, qq = lane&15 covers q-quad (qbase + 4*qq .. +3). Own-n warps
// ((wid>>2)==rank) never wait; others wait on one mbarrier fed by 3 bulk
// 256B copies (expect_tx = 768).
__global__ void __cluster_dims__(CL, 1, 1) __launch_bounds__(NT, 1)
k_forward(const int* __restrict__ xs) {
    __shared__ __align__(16) float cbuf[2][SS];       // full chart, dbl buffered
    __shared__ __align__(16) float sew[16][16];       // per-warp se slice
    __shared__ __align__(16) float spart[16][64];     // 16 n-groups x 64 q
    __shared__ int   sx[LL];
    __shared__ __align__(8) unsigned long long bars[2];

    const int tid  = threadIdx.x;
    const int lane = tid & 31, wid = tid >> 5;
    const int lh = lane >> 4, qq = lane & 15;
    const unsigned rank = (unsigned)(blockIdx.x & (CL - 1));
    const int b  = blockIdx.x >> 2;
    const int qbase = (int)rank * 64;
    const bool ownw = ((wid >> 2) == (int)rank);      // warp's n-range is local

    sx[tid] = xs[b * LL + tid];
    if (tid < SS) cbuf[0][tid] = g_c0[tid];
    if (tid == 0) {
        asm volatile("mbarrier.init.shared.b64 [%0], %1;"
                     :: "r"(smem_u32(&bars[0])), "r"(1) : "memory");
        asm volatile("mbarrier.init.shared.b64 [%0], %1;"
                     :: "r"(smem_u32(&bars[1])), "r"(1) : "memory");
    }
    __syncthreads();
    cluster_sync_();   // inits visible before any bulk copy

    const unsigned bar0_loc = smem_u32(&bars[0]);
    const unsigned bar1_loc = smem_u32(&bars[1]);
    const unsigned src_loc0 = smem_u32(&cbuf[0][qbase]);
    const unsigned src_loc1 = smem_u32(&cbuf[1][qbase]);
    // per-peer remote targets (our own chunk slot in each peer's buffers)
    unsigned dst_rem0[3], dst_rem1[3], bar_rem0[3], bar_rem1[3];
    {
        int k = 0;
#pragma unroll
        for (unsigned pr = 0; pr < CL; ++pr) {
            if (pr == rank) continue;
            dst_rem0[k] = mapa_u32(src_loc0, pr);
            dst_rem1[k] = mapa_u32(src_loc1, pr);
            bar_rem0[k] = mapa_u32(bar0_loc, pr);
            bar_rem1[k] = mapa_u32(bar1_loc, pr);
            ++k;
        }
    }

    uint4 PF[4];   // 4 npairs x (4 q x 2 n) bf16

    // uint4 index: (x<<13) + npair*64 + global_q/4 ; npair = 8*wid + 4*lh + j
#define PFETCH(xv) do {                                                            \
    const uint4* _mp = (const uint4*)g_M2 + (((size_t)(unsigned)(xv)) << 13)       \
        + (unsigned)(((wid << 3) + (lh << 2)) << 6)                                \
        + (unsigned)((qbase >> 2) + qq);                                           \
    _Pragma("unroll")                                                              \
    for (int _j = 0; _j < 4; _j++) PF[_j] = __ldg(_mp + (_j << 6));                \
} while (0)

    float gcur = (tid < 64) ? g_Gtab[sx[LL - 1] * SS + qbase + tid] : 0.0f;
    PFETCH(sx[LL - 1]);

    unsigned ph0 = 0, ph1 = 0;
#pragma unroll 1
    for (int s = 0; s < LL; ++s) {
        const int p = s & 1, np = p ^ 1;
        const int x = sx[LL - 1 - s];

        // arm receive barrier for the 3 incoming 256B copies of this step
        if (tid == 0)
            asm volatile("mbarrier.arrive.expect_tx.shared.b64 _, [%0], %1;"
                         :: "r"(np ? bar1_loc : bar0_loc), "r"(768) : "memory");
        __syncthreads();                       // S1: local chart writes visible

        if (s) {
            unsigned& ph = p ? ph1 : ph0;
            if (!ownw) mbar_wait_cta(p ? bar1_loc : bar0_loc, ph);
            ph ^= 1;                           // all threads track parity
        }

        // CTA-local shift: own chunk's first element (always local)
        float cmaxl = cbuf[p][qbase];
        if (lane < 16)
            sew[wid][lane] = __expf(cbuf[p][(wid << 4) + lane] - cmaxl);
        __syncwarp();

        // lane covers 4 npairs (j), 4 consecutive q (quad qq)
        float a0 = 0.f, a1 = 0.f, a2 = 0.f, a3 = 0.f;
        const float2* sw2 = (const float2*)&sew[wid][lh << 3];
#pragma unroll
        for (int j = 0; j < 4; ++j) {
            float2 sp = sw2[j];                // se for (n even, n odd)
            uint4 v = PF[j];
            a0 = fmaf(__uint_as_float(v.x << 16),         sp.x, a0);
            a0 = fmaf(__uint_as_float(v.x & 0xFFFF0000u), sp.y, a0);
            a1 = fmaf(__uint_as_float(v.y << 16),         sp.x, a1);
            a1 = fmaf(__uint_as_float(v.y & 0xFFFF0000u), sp.y, a1);
            a2 = fmaf(__uint_as_float(v.z << 16),         sp.x, a2);
            a2 = fmaf(__uint_as_float(v.z & 0xFFFF0000u), sp.y, a2);
            a3 = fmaf(__uint_as_float(v.w << 16),         sp.x, a3);
            a3 = fmaf(__uint_as_float(v.w & 0xFFFF0000u), sp.y, a3);
        }
        // combine the two 8-n halves (lanes l and l+16 share the q-quad)
        a0 += __shfl_xor_sync(0xffffffffu, a0, 16);
        a1 += __shfl_xor_sync(0xffffffffu, a1, 16);
        a2 += __shfl_xor_sync(0xffffffffu, a2, 16);
        a3 += __shfl_xor_sync(0xffffffffu, a3, 16);
        if (lane < 16)
            *(float4*)&spart[wid][qq << 2] = make_float4(a0, a1, a2, a3);

        // prefetch next step's M and G while partials settle / peers lag
        int xn = (s + 1 < LL) ? sx[LL - 2 - s] : 0;
        PFETCH(xn);
        float gnext = (tid < 64) ? g_Gtab[xn * SS + qbase + tid] : 0.0f;

        __syncthreads();                       // S3: partials visible

        if (tid < 64) {
            float ssum = 0.f;
#pragma unroll
            for (int g = 0; g < 16; ++g) ssum += spart[g][tid];
            float nc = (x != 0) ? (gcur + __logf(ssum) + cmaxl)
                                : cbuf[p][qbase + tid];       // padding passthrough
            cbuf[np][qbase + tid] = nc;                       // own chunk, local STS
            asm volatile("bar.sync 1, 64;" ::: "memory");     // reducer warps only
            if (tid == 0) {
                asm volatile("fence.proxy.async.shared::cta;" ::: "memory");
#pragma unroll
                for (int k = 0; k < 3; ++k) {
                    asm volatile(
                        "cp.async.bulk.shared::cluster.shared::cta.mbarrier::complete_tx::bytes "
                        "[%0], [%1], %2, [%3];"
                        :: "r"(np ? dst_rem1[k] : dst_rem0[k]),
                           "r"(np ? src_loc1 : src_loc0),
                           "r"(256),
                           "r"(np ? bar_rem1[k] : bar_rem0[k]) : "memory");
                }
            }
        }
        gcur = gnext;
    }

    // step 511 wrote into cbuf[0] / bars[0] (phase parity = ph0)
    mbar_wait_cta(bar0_loc, ph0);
    __syncthreads();

    if (rank == 0 && wid == 0) {
        float vv[8];
        float m = -3.0e38f;
#pragma unroll
        for (int i = 0; i < 8; i++) {
            vv[i] = g_LAl[lane + 32 * i] + cbuf[0][lane + 32 * i];
            m = fmaxf(m, vv[i]);
        }
        m = wredMax(m);
        float sacc = 0.0f;
#pragma unroll
        for (int i = 0; i < 8; i++) sacc += __expf(vv[i] - m);
        sacc = wredSum(sacc);
        if (lane == 0) g_perseq[b] = __logf(sacc) + m;
    }
    cluster_sync_();   // no CTA exits while peer bulk copies may target it
#undef PFETCH
}

// -------- K6: out = sum_b per_seq[b] --------
__global__ void k_final(float* __restrict__ out) {
    float v = (threadIdx.x < BB) ? g_perseq[threadIdx.x] : 0.0f;
    v = wredSum(v);
    if (threadIdx.x == 0) out[0] = v;
}

// ============================================================================
extern "C" void kernel_launch(void* const* d_in, const int* in_sizes, int n_in,
                              void* d_out, int out_size) {
    const int*   xs    = (const int*)d_in[0];
    const float* alpha = (const float*)d_in[1];
    const float* omega = (const float*)d_in[2];
    const float* E     = (const float*)d_in[3];
    const float* T     = (const float*)d_in[4];
    float* out = (float*)d_out;

    k_rowconst_T<<<(SS * SS) / 8, 256>>>(T);
    k_small<<<33, 256>>>(E, alpha, omega);
    k_gtab<<<SS, 256>>>(E);
    k_buildM<<<dim3(8, 8, SS), dim3(32, 8)>>>(T);
    k_forward<<<BB * CL, NT>>>(xs);       // 16 clusters x 4 CTAs x 512 threads
    k_final<<<1, 32>>>(out);
}